// round 12
// baseline (speedup 1.0000x reference)
#include <cuda_runtime.h>

// out[b, idx] = prod_w ( bit_{19-w}(idx) ? sin(h[b,w]) : cos(h[b,w]) ),
// h = (x + params) * 0.5. Wire w maps to idx bit (19-w).
//
// FINAL (frozen, reproduced twice at 40.93 us):
// The reference circuit applies one RY per distinct wire to |0..0>, so the
// state is a product state: out factorizes into 20 per-wire cos/sin factors.
// This reduces the problem to a 268 MB coalesced write stream.
//
// Layout: 16384 CTAs (256 hi-groups x 64 batches). CTA = (batch b, 4
// contiguous hi values), storing one contiguous 16 KB region. All products
// are computed in registers via shared-prefix factoring (lo = 4*tid+j and
// hi = 4*bx+i share bits 2..9), ~35 muls/thread, one barrier, no smem tables.
// Stores are __stcs (evict-first): write-once output, keep L2 clean.
//
// Measured: 40.93 us = 6.56 TB/s sustained write = 82% of HBM spec.
// Bracketing evidence: grid 1024->49.2, 4096->43.0, 8192->41.5,
// 16384->40.9 (min), 32768->43.0. TMA bulk-store path: neutral.
// L2-residency store-policy split: regression. DRAM-write floor reached.

#define N_WIRES 20
#define BATCH 64
#define HI_PER_BLOCK 4
#define THREADS 256

__global__ __launch_bounds__(THREADS, 8)
void qansatz_kernel(const float* __restrict__ x,
                    const float* __restrict__ params,
                    float* __restrict__ out)
{
    __shared__ float sc[N_WIRES];
    __shared__ float ss[N_WIRES];

    const int b   = blockIdx.y;          // batch
    const int bx  = blockIdx.x;          // hi_base = 4*bx
    const int tid = threadIdx.x;

    // 1) cos/sin for this batch's 20 wires (one barrier)
    if (tid < N_WIRES) {
        float h = (x[b * N_WIRES + tid] + params[tid]) * 0.5f;
        float c, s;
        sincosf(h, &s, &c);
        sc[tid] = c;
        ss[tid] = s;
    }
    __syncthreads();

    // 2) lo part: this thread covers lo = 4*tid + j, j=0..3.
    //    lo bit q (q=2..9) = tid bit (q-2); factor = ss[19-q] : sc[19-q].
    float lo_common = 1.0f;
    #pragma unroll
    for (int q = 2; q < 10; q++)
        lo_common *= ((tid >> (q - 2)) & 1) ? ss[19 - q] : sc[19 - q];

    // j bit0 -> wire 19, j bit1 -> wire 18
    float lv0 = sc[19] * sc[18];   // j=0
    float lv1 = ss[19] * sc[18];   // j=1
    float lv2 = sc[19] * ss[18];   // j=2
    float lv3 = ss[19] * ss[18];   // j=3

    // 3) hi part: hi = 4*bx + i, i=0..3.
    //    hi bit q (q=2..9) = bx bit (q-2); factor = ss[9-q] : sc[9-q].
    float hi_common = 1.0f;
    #pragma unroll
    for (int q = 2; q < 10; q++)
        hi_common *= ((bx >> (q - 2)) & 1) ? ss[9 - q] : sc[9 - q];

    // i bit0 -> wire 9, i bit1 -> wire 8
    float hv[4];
    hv[0] = sc[9] * sc[8];     // i=0
    hv[1] = ss[9] * sc[8];     // i=1
    hv[2] = sc[9] * ss[8];     // i=2
    hv[3] = ss[9] * ss[8];     // i=3

    float base = lo_common * hi_common;
    float c0 = base * lv0, c1 = base * lv1, c2 = base * lv2, c3 = base * lv3;

    // 4) stream out: 4 hi-values x one float4/thread (independent stores)
    size_t off = ((size_t)b << 20) + ((size_t)bx << 12);
    float4* dst = reinterpret_cast<float4*>(out + off) + tid;

    #pragma unroll
    for (int i = 0; i < HI_PER_BLOCK; i++) {
        float ph = hv[i];
        float4 v;
        v.x = ph * c0;
        v.y = ph * c1;
        v.z = ph * c2;
        v.w = ph * c3;
        __stcs(dst + i * 256, v);    // streaming store: write-once output
    }
}

extern "C" void kernel_launch(void* const* d_in, const int* in_sizes, int n_in,
                              void* d_out, int out_size)
{
    const float* x      = (const float*)d_in[0];   // (64, 20)
    const float* params = (const float*)d_in[1];   // (20,)
    float* out          = (float*)d_out;           // (64, 2^20)

    dim3 grid(1024 / HI_PER_BLOCK, BATCH);         // (256, 64) = 16384 CTAs
    qansatz_kernel<<<grid, THREADS>>>(x, params, out);
}